// round 4
// baseline (speedup 1.0000x reference)
#include <cuda_runtime.h>
#include <math.h>

#define NF 256
#define NS 65536
#define NC 2000
#define NCP 2048
#define NB 256
#define CAP 128
#define TEMPv 0.05f
#define INS_TEMPv 0.09f
#define GC 16
#define NGRP (NC / GC)        // 125 class groups

// ---- scratch (device globals; no allocations) ----
__device__ int   g_cnt1[NCP];
__device__ int   g_cnt2[NCP];
__device__ int   g_list1[NC * CAP];
__device__ int   g_list2[NC * CAP];
__device__ int   g_targ[NB];
__device__ int   g_targ2[NB];
__device__ float g_centT[NGRP * NF * GC];  // [grp][k][g]: scaled centroids, transposed
__device__ float g_in4[NF * NB];           // packed: float4 (k/4)*NB + b holds k..k+3 of b
__device__ float g_fsum[NB];               // focal softmax denominator partials
__device__ float g_ftgt[NB];               // focal target-class exp
__device__ float g_acc[2];                 // (unused, ins_sum)
__device__ int   g_done = 0;               // last-block ticket (self-resetting)

// ---- K0: zero counters/accumulators, compute per-sample targets ----
__global__ void k_init(const int* __restrict__ labels, const int* __restrict__ labels2,
                       const int* __restrict__ indexes) {
    int i = blockIdx.x * blockDim.x + threadIdx.x;
    if (i < NCP) { g_cnt1[i] = 0; g_cnt2[i] = 0; }
    if (i < NB) {
        int idx = indexes[i];
        g_targ[i]  = labels[idx];
        g_targ2[i] = labels2[idx];
        g_fsum[i] = 0.f;
        g_ftgt[i] = 0.f;
    }
    if (i < 2) g_acc[i] = 0.f;
}

// ---- K1: scatter member indices into fixed-capacity buckets + pack inputs ----
__global__ void k_scatter(const int* __restrict__ labels, const int* __restrict__ labels2,
                          const float* __restrict__ inputs) {
    int i = blockIdx.x * blockDim.x + threadIdx.x;
    int c1 = labels[i];
    int p1 = atomicAdd(&g_cnt1[c1], 1);
    if (p1 < CAP) g_list1[c1 * CAP + p1] = i;
    int c2 = labels2[i];
    int p2 = atomicAdd(&g_cnt2[c2], 1);
    if (p2 < CAP) g_list2[c2 * CAP + p2] = i;
    // pack inputs: sample b, feature k  ->  float slot ((k>>2)*NB + b)*4 + (k&3)
    int b = i >> 8, k = i & 255;
    g_in4[(((k >> 2) * NB) + b) * 4 + (k & 3)] = inputs[i];
}

// ---- K2: scaled class centroids (HBM pass: 64 MB) -> transposed layout ----
// 512 thr = 8 row slots x 64 float4 lanes; 2-stage pipeline for MLP.
__global__ void k_centroid(const float* __restrict__ features) {
    int c   = blockIdx.x;
    int tid = threadIdx.x;
    int r   = tid >> 6;        // 0..7 row slot
    int f4  = tid & 63;        // float4 column
    int cnt = min(g_cnt1[c], CAP);
    __shared__ int js[CAP];
    if (tid < cnt) js[tid] = g_list1[c * CAP + tid];
    __syncthreads();
    float4 acc = make_float4(0.f, 0.f, 0.f, 0.f);
    int k = r;
    if (k < cnt) {
        float4 v0 = ((const float4*)(features + (size_t)js[k] * NF))[f4];
        for (k += 8; k < cnt; k += 8) {
            float4 v1 = ((const float4*)(features + (size_t)js[k] * NF))[f4];
            acc.x += v0.x; acc.y += v0.y; acc.z += v0.z; acc.w += v0.w;
            v0 = v1;
        }
        acc.x += v0.x; acc.y += v0.y; acc.z += v0.z; acc.w += v0.w;
    }
    __shared__ float4 sred[8][64];
    sred[r][f4] = acc;
    __syncthreads();
    if (r == 0) {
        float4 s = acc;
#pragma unroll
        for (int w = 1; w < 8; w++) {
            float4 a = sred[w][f4];
            s.x += a.x; s.y += a.y; s.z += a.z; s.w += a.w;
        }
        float sc = (cnt > 0) ? (1.f / (TEMPv * (float)cnt)) : 0.f;
        // transposed store: g_centT[(c>>4)][k][c&15]
        float* dst = g_centT + (size_t)(c >> 4) * (NF * GC) + (c & 15);
        dst[(4 * f4 + 0) * GC] = s.x * sc;
        dst[(4 * f4 + 1) * GC] = s.y * sc;
        dst[(4 * f4 + 2) * GC] = s.z * sc;
        dst[(4 * f4 + 3) * GC] = s.w * sc;
    }
}

// ---- K3: fused sim GEMM + masked-softmax partials (f32x2, split-k) ----
// grid 250 = 125 class-groups x 2 b-halves. Block: 16 classes x 128 b,
// 256 threads = 2 k-halves per b. FFMA2 inner loop.
__global__ void __launch_bounds__(256) k_simfocal() {
    int cg = blockIdx.x >> 1;
    int bh = blockIdx.x & 1;
    int tid = threadIdx.x;
    int bl = tid & 127;
    int kh = tid >> 7;
    int b  = bh * 128 + bl;

    __shared__ float4 cent4[NF * GC / 4];          // 16 KB, [k][g] transposed
    float* cent = (float*)cent4;
    const float4* src = (const float4*)(g_centT + (size_t)cg * (NF * GC));
    for (int t = tid; t < NF * GC / 4; t += 256) cent4[t] = src[t];
    __syncthreads();

    unsigned long long acc2[8];
#pragma unroll
    for (int q = 0; q < 8; q++) acc2[q] = 0ULL;

    const float4* xp = (const float4*)g_in4;
    int k4beg = kh * 32;
#pragma unroll 4
    for (int k4 = k4beg; k4 < k4beg + 32; k4++) {
        float4 x = xp[k4 * NB + b];                // coalesced LDG.128
        float xs[4] = {x.x, x.y, x.z, x.w};
#pragma unroll
        for (int j = 0; j < 4; j++) {
            int k = 4 * k4 + j;
            unsigned int xu = __float_as_uint(xs[j]);
            unsigned long long xx;
            asm("mov.b64 %0, {%1, %1};" : "=l"(xx) : "r"(xu));
            const ulonglong2* cp = (const ulonglong2*)(cent + k * GC);
#pragma unroll
            for (int q = 0; q < 4; q++) {
                ulonglong2 cv = cp[q];             // LDS.128 broadcast
                asm("fma.rn.f32x2 %0, %1, %2, %0;" : "+l"(acc2[2*q])   : "l"(cv.x), "l"(xx));
                asm("fma.rn.f32x2 %0, %1, %2, %0;" : "+l"(acc2[2*q+1]) : "l"(cv.y), "l"(xx));
            }
        }
    }

    // split-k combine
    __shared__ unsigned long long sp[128][9];      // pad stride 9
    if (kh) {
#pragma unroll
        for (int q = 0; q < 8; q++) sp[bl][q] = acc2[q];
    }
    __syncthreads();
    if (!kh) {
        float s[16];
#pragma unroll
        for (int q = 0; q < 8; q++) {
            union { unsigned long long u; float2 f; } a, o;
            a.u = acc2[q]; o.u = sp[bl][q];
            s[2*q]   = a.f.x + o.f.x;
            s[2*q+1] = a.f.y + o.f.y;
        }
        int tb = g_targ[b];
        float local = 0.f;
#pragma unroll
        for (int g = 0; g < GC; g++) {
            int c = cg * GC + g;
            if (g_cnt1[c] > 0) {
                float e = expf(s[g]);              // centroid pre-scaled by 1/(TEMP*nums)
                local += e;
                if (c == tb) g_ftgt[b] = e;        // unique writer per b
            }
        }
        atomicAdd(&g_fsum[b], local);
    }
}

// ---- K4: instance loss (sparse) + last-block final combine ----
__global__ void k_insfinal(const float* __restrict__ inputs, const float* __restrict__ features,
                           const int* __restrict__ labels, const int* __restrict__ labels2,
                           const float* __restrict__ mask_in,
                           const int* __restrict__ epoch_p, const int* __restrict__ back_p,
                           float* __restrict__ out) {
    int b  = blockIdx.x;
    int t  = g_targ[b];
    int t2 = g_targ2[b];
    __shared__ float4 inp[NF / 4];
    if (threadIdx.x < NF / 4)
        inp[threadIdx.x] = ((const float4*)(inputs + b * NF))[threadIdx.x];
    __syncthreads();
    int wid = threadIdx.x >> 5, lane = threadIdx.x & 31;
    float pos = 0.f, neg = 0.f;
    int np = 0, nn = 0;
    {
        int cnt = min(g_cnt1[t], CAP);
        for (int k = wid; k < cnt; k += 8) {
            int j = g_list1[t * CAP + k];
            if (labels2[j] != t2) {               // in_a & ~in_b
                const float4* fr = (const float4*)(features + (size_t)j * NF);
                float d = 0.f;
#pragma unroll
                for (int q = 0; q < 2; q++) {
                    int idx = lane + q * 32;
                    float4 f = fr[idx], u = inp[idx];
                    d += f.x * u.x + f.y * u.y + f.z * u.z + f.w * u.w;
                }
                for (int o = 16; o; o >>= 1) d += __shfl_xor_sync(0xFFFFFFFFu, d, o);
                if (lane == 0) { pos += expf(d / INS_TEMPv); np++; }
            }
        }
    }
    {
        int cnt = min(g_cnt2[t2], CAP);
        for (int k = wid; k < cnt; k += 8) {
            int j = g_list2[t2 * CAP + k];
            if (labels[j] != t) {                 // in_b & ~in_a
                const float4* fr = (const float4*)(features + (size_t)j * NF);
                float d = 0.f;
#pragma unroll
                for (int q = 0; q < 2; q++) {
                    int idx = lane + q * 32;
                    float4 f = fr[idx], u = inp[idx];
                    d += f.x * u.x + f.y * u.y + f.z * u.z + f.w * u.w;
                }
                for (int o = 16; o; o >>= 1) d += __shfl_xor_sync(0xFFFFFFFFu, d, o);
                if (lane == 0) { neg += expf(d / INS_TEMPv); nn++; }
            }
        }
    }
    __shared__ float rp[8], rn[8];
    __shared__ int rnp[8], rnn[8];
    if (lane == 0) { rp[wid] = pos; rn[wid] = neg; rnp[wid] = np; rnn[wid] = nn; }
    __syncthreads();
    if (threadIdx.x == 0) {
        float P = 0.f, Ng = 0.f; int NP = 0, NN = 0;
        for (int w = 0; w < 8; w++) { P += rp[w]; Ng += rn[w]; NP += rnp[w]; NN += rnn[w]; }
        float per = 0.f;
        if (NP > 0 && NN > 0) {
            float insv = P / (P + Ng + 1e-6f);
            per = -logf(insv + 1e-6f) / (float)NP;
        }
        atomicAdd(&g_acc[1], per);
    }

    // ---- last-block final combine ----
    __threadfence();
    __shared__ int isLast;
    if (threadIdx.x == 0) {
        int ticket = atomicAdd(&g_done, 1);
        isLast = (ticket == NB - 1);
    }
    __syncthreads();
    if (isLast) {
        __threadfence();
        int bb = threadIdx.x;
        float p  = g_ftgt[bb] / (g_fsum[bb] + 1e-6f);
        float om = 1.f - p;
        float fb = -om * om * logf(p + 1e-6f);
        const float4* a = (const float4*)(inputs  + bb * NF);
        const float4* m = (const float4*)(mask_in + bb * NF);
        float na = 0.f, nm = 0.f, d = 0.f;
        for (int k = 0; k < NF / 4; k++) {
            float4 x = a[k], y = m[k];
            na += x.x * x.x + x.y * x.y + x.z * x.z + x.w * x.w;
            nm += y.x * y.x + y.y * y.y + y.z * y.z + y.w * y.w;
            d  += x.x * y.x + x.y * y.y + x.z * y.z + x.w * y.w;
        }
        float cv = d / (sqrtf(na) * sqrtf(nm));
        __shared__ float sf[256], sc2[256];
        sf[bb] = fb; sc2[bb] = cv;
        __syncthreads();
        for (int o = 128; o > 0; o >>= 1) {
            if (bb < o) { sf[bb] += sf[bb + o]; sc2[bb] += sc2[bb + o]; }
            __syncthreads();
        }
        if (bb == 0) {
            float focal   = sf[0] / (float)NB;
            float contras = -sc2[0] / (float)NB;
            float insv    = g_acc[1] / (float)NB;
            int epoch = epoch_p[0];
            int back  = back_p[0];
            float loss;
            if (back == 1) {
                loss = focal + 0.25f * contras;
                if (epoch >= 30) loss += 0.2f * insv;
            } else if (back == 2) {
                loss = focal + 0.25f * contras;
            } else {
                loss = focal;
            }
            out[0] = loss;
            g_done = 0;   // reset for next graph replay
        }
    }
}

extern "C" void kernel_launch(void* const* d_in, const int* in_sizes, int n_in,
                              void* d_out, int out_size) {
    const float* inputs   = (const float*)d_in[0];
    const float* mask_in  = (const float*)d_in[1];
    const float* features = (const float*)d_in[2];
    const int*   labels   = (const int*)d_in[3];
    const int*   labels2  = (const int*)d_in[4];
    const int*   indexes  = (const int*)d_in[5];
    const int*   epoch_p  = (const int*)d_in[6];
    const int*   back_p   = (const int*)d_in[7];
    float*       out      = (float*)d_out;

    k_init<<<8, 256>>>(labels, labels2, indexes);
    k_scatter<<<NS / 256, 256>>>(labels, labels2, inputs);
    k_centroid<<<NC, 512>>>(features);
    k_simfocal<<<2 * NGRP, 256>>>();
    k_insfinal<<<NB, 256>>>(inputs, features, labels, labels2, mask_in, epoch_p, back_p, out);
}

// round 5
// speedup vs baseline: 1.0317x; 1.0317x over previous
#include <cuda_runtime.h>
#include <math.h>

#define NF 256
#define NS 65536
#define NC 2000
#define NCP 2048
#define NB 256
#define CAP 128
#define TEMPv 0.05f
#define INS_TEMPv 0.09f
#define GC 16
#define NGRP (NC / GC)        // 125 class groups

// ---- scratch (device globals; all zero-init, self-resetting each run) ----
__device__ int   g_cnt1[NCP];
__device__ int   g_cnt2[NCP];
__device__ int   g_list1[NC * CAP];
__device__ int   g_list2[NC * CAP];
__device__ int   g_targ[NB];
__device__ int   g_targ2[NB];
__device__ float g_centT[NGRP * NF * GC];  // [grp][k][g]: scaled centroids, transposed
__device__ float g_in4[NF * NB];           // packed: float4 (k/4)*NB + b holds k..k+3 of b
__device__ float g_fsum[NB];               // focal softmax denominator partials
__device__ float g_ftgt[NB];               // focal target-class exp
__device__ float g_ins;                    // ins_sum
__device__ int   g_done;                   // last-block ticket

// ---- K1: scatter into fixed-capacity buckets + pack inputs + targets ----
// Counters were zeroed by previous run's k_insfinal (or static zero-init).
__global__ void k_scatter(const int* __restrict__ labels, const int* __restrict__ labels2,
                          const float* __restrict__ inputs, const int* __restrict__ indexes) {
    int i = blockIdx.x * blockDim.x + threadIdx.x;
    int c1 = labels[i];
    int p1 = atomicAdd(&g_cnt1[c1], 1);
    if (p1 < CAP) g_list1[c1 * CAP + p1] = i;
    int c2 = labels2[i];
    int p2 = atomicAdd(&g_cnt2[c2], 1);
    if (p2 < CAP) g_list2[c2 * CAP + p2] = i;
    // pack inputs: sample b, feature k  ->  float slot ((k>>2)*NB + b)*4 + (k&3)
    int b = i >> 8, k = i & 255;
    g_in4[(((k >> 2) * NB) + b) * 4 + (k & 3)] = inputs[i];
    if (i < NB) {
        int idx = indexes[i];
        g_targ[i]  = labels[idx];
        g_targ2[i] = labels2[idx];
    }
}

// ---- K2: scaled class centroids (HBM pass: 64 MB) -> transposed layout ----
__global__ void k_centroid(const float* __restrict__ features) {
    int c   = blockIdx.x;
    int tid = threadIdx.x;
    int r   = tid >> 6;        // 0..7 row slot
    int f4  = tid & 63;        // float4 column
    int cnt = min(g_cnt1[c], CAP);
    __shared__ int js[CAP];
    if (tid < cnt) js[tid] = g_list1[c * CAP + tid];
    __syncthreads();
    float4 acc = make_float4(0.f, 0.f, 0.f, 0.f);
    int k = r;
    if (k < cnt) {
        float4 v0 = ((const float4*)(features + (size_t)js[k] * NF))[f4];
        for (k += 8; k < cnt; k += 8) {
            float4 v1 = ((const float4*)(features + (size_t)js[k] * NF))[f4];
            acc.x += v0.x; acc.y += v0.y; acc.z += v0.z; acc.w += v0.w;
            v0 = v1;
        }
        acc.x += v0.x; acc.y += v0.y; acc.z += v0.z; acc.w += v0.w;
    }
    __shared__ float4 sred[8][64];
    sred[r][f4] = acc;
    __syncthreads();
    if (r == 0) {
        float4 s = acc;
#pragma unroll
        for (int w = 1; w < 8; w++) {
            float4 a = sred[w][f4];
            s.x += a.x; s.y += a.y; s.z += a.z; s.w += a.w;
        }
        float sc = (cnt > 0) ? (1.f / (TEMPv * (float)cnt)) : 0.f;
        float* dst = g_centT + (size_t)(c >> 4) * (NF * GC) + (c & 15);
        dst[(4 * f4 + 0) * GC] = s.x * sc;
        dst[(4 * f4 + 1) * GC] = s.y * sc;
        dst[(4 * f4 + 2) * GC] = s.z * sc;
        dst[(4 * f4 + 3) * GC] = s.w * sc;
    }
}

// ---- K3: fused sim GEMM + masked-softmax partials ----
// grid 250 = 125 class-groups x 2 b-halves. Block 512 thr = 128 b x 4 k-quarters.
// 27 warps/SM; f32x2 inner loop; ordered smem split-k reduction.
__global__ void __launch_bounds__(512) k_simfocal() {
    int cg = blockIdx.x >> 1;
    int bh = blockIdx.x & 1;
    int tid = threadIdx.x;
    int bl = tid & 127;
    int kq = tid >> 7;                 // 0..3
    int b  = bh * 128 + bl;

    __shared__ float4 cent4[NF * GC / 4];          // 16 KB, [k][g] transposed
    __shared__ float  sredk[3 * 128 * 17];         // 25.5 KB split-k staging
    float* cent = (float*)cent4;
    const float4* src = (const float4*)(g_centT + (size_t)cg * (NF * GC));
    for (int t = tid; t < NF * GC / 4; t += 512) cent4[t] = src[t];
    __syncthreads();

    unsigned long long acc2[8];
#pragma unroll
    for (int q = 0; q < 8; q++) acc2[q] = 0ULL;

    const float4* xp = (const float4*)g_in4;
    int k4beg = kq * 16;
#pragma unroll 4
    for (int k4 = k4beg; k4 < k4beg + 16; k4++) {
        float4 x = xp[k4 * NB + b];                // coalesced LDG.128
        float xs[4] = {x.x, x.y, x.z, x.w};
#pragma unroll
        for (int j = 0; j < 4; j++) {
            int k = 4 * k4 + j;
            unsigned int xu = __float_as_uint(xs[j]);
            unsigned long long xx;
            asm("mov.b64 %0, {%1, %1};" : "=l"(xx) : "r"(xu));
            const ulonglong2* cp = (const ulonglong2*)(cent + k * GC);
#pragma unroll
            for (int q = 0; q < 4; q++) {
                ulonglong2 cv = cp[q];             // LDS.128 broadcast
                asm("fma.rn.f32x2 %0, %1, %2, %0;" : "+l"(acc2[2*q])   : "l"(cv.x), "l"(xx));
                asm("fma.rn.f32x2 %0, %1, %2, %0;" : "+l"(acc2[2*q+1]) : "l"(cv.y), "l"(xx));
            }
        }
    }

    // ordered split-k combine (stride-17 => bank-conflict-free)
    if (kq) {
        float* dst = sredk + ((kq - 1) * 128 + bl) * 17;
#pragma unroll
        for (int q = 0; q < 8; q++) {
            union { unsigned long long u; float2 f; } a; a.u = acc2[q];
            dst[2 * q]     = a.f.x;
            dst[2 * q + 1] = a.f.y;
        }
    }
    __syncthreads();
    if (kq == 0) {
        float s[16];
#pragma unroll
        for (int q = 0; q < 8; q++) {
            union { unsigned long long u; float2 f; } a; a.u = acc2[q];
            s[2 * q] = a.f.x; s[2 * q + 1] = a.f.y;
        }
#pragma unroll
        for (int r = 0; r < 3; r++) {
            const float* sp2 = sredk + (r * 128 + bl) * 17;
#pragma unroll
            for (int g = 0; g < 16; g++) s[g] += sp2[g];
        }
        int tb = g_targ[b];
        float local = 0.f;
#pragma unroll
        for (int g = 0; g < GC; g++) {
            int c = cg * GC + g;
            if (g_cnt1[c] > 0) {
                float e = expf(s[g]);              // centroid pre-scaled by 1/(TEMP*nums)
                local += e;
                if (c == tb) g_ftgt[b] = e;        // unique writer per b
            }
        }
        atomicAdd(&g_fsum[b], local);
    }
}

// ---- K4: instance loss (sparse) + last-block final combine + state reset ----
__global__ void k_insfinal(const float* __restrict__ inputs, const float* __restrict__ features,
                           const int* __restrict__ labels, const int* __restrict__ labels2,
                           const float* __restrict__ mask_in,
                           const int* __restrict__ epoch_p, const int* __restrict__ back_p,
                           float* __restrict__ out) {
    int b  = blockIdx.x;
    int t  = g_targ[b];
    int t2 = g_targ2[b];
    __shared__ float4 inp[NF / 4];
    if (threadIdx.x < NF / 4)
        inp[threadIdx.x] = ((const float4*)(inputs + b * NF))[threadIdx.x];
    __syncthreads();
    int wid = threadIdx.x >> 5, lane = threadIdx.x & 31;
    float pos = 0.f, neg = 0.f;
    int np = 0, nn = 0;
    {
        int cnt = min(g_cnt1[t], CAP);
        for (int k = wid; k < cnt; k += 8) {
            int j = g_list1[t * CAP + k];
            if (labels2[j] != t2) {               // in_a & ~in_b
                const float4* fr = (const float4*)(features + (size_t)j * NF);
                float d = 0.f;
#pragma unroll
                for (int q = 0; q < 2; q++) {
                    int idx = lane + q * 32;
                    float4 f = fr[idx], u = inp[idx];
                    d += f.x * u.x + f.y * u.y + f.z * u.z + f.w * u.w;
                }
                for (int o = 16; o; o >>= 1) d += __shfl_xor_sync(0xFFFFFFFFu, d, o);
                if (lane == 0) { pos += expf(d / INS_TEMPv); np++; }
            }
        }
    }
    {
        int cnt = min(g_cnt2[t2], CAP);
        for (int k = wid; k < cnt; k += 8) {
            int j = g_list2[t2 * CAP + k];
            if (labels[j] != t) {                 // in_b & ~in_a
                const float4* fr = (const float4*)(features + (size_t)j * NF);
                float d = 0.f;
#pragma unroll
                for (int q = 0; q < 2; q++) {
                    int idx = lane + q * 32;
                    float4 f = fr[idx], u = inp[idx];
                    d += f.x * u.x + f.y * u.y + f.z * u.z + f.w * u.w;
                }
                for (int o = 16; o; o >>= 1) d += __shfl_xor_sync(0xFFFFFFFFu, d, o);
                if (lane == 0) { neg += expf(d / INS_TEMPv); nn++; }
            }
        }
    }
    __shared__ float rp[8], rn[8];
    __shared__ int rnp[8], rnn[8];
    if (lane == 0) { rp[wid] = pos; rn[wid] = neg; rnp[wid] = np; rnn[wid] = nn; }
    __syncthreads();
    if (threadIdx.x == 0) {
        float P = 0.f, Ng = 0.f; int NP = 0, NN = 0;
        for (int w = 0; w < 8; w++) { P += rp[w]; Ng += rn[w]; NP += rnp[w]; NN += rnn[w]; }
        float per = 0.f;
        if (NP > 0 && NN > 0) {
            float insv = P / (P + Ng + 1e-6f);
            per = -logf(insv + 1e-6f) / (float)NP;
        }
        atomicAdd(&g_ins, per);
    }

    // ---- last-block final combine + reset all scratch for next replay ----
    __threadfence();
    __shared__ int isLast;
    if (threadIdx.x == 0) {
        int ticket = atomicAdd(&g_done, 1);
        isLast = (ticket == NB - 1);
    }
    __syncthreads();
    if (isLast) {
        __threadfence();
        int bb = threadIdx.x;
        float p  = g_ftgt[bb] / (g_fsum[bb] + 1e-6f);
        g_ftgt[bb] = 0.f;                          // reset for next replay
        g_fsum[bb] = 0.f;
        float om = 1.f - p;
        float fb = -om * om * logf(p + 1e-6f);
        const float4* a = (const float4*)(inputs  + bb * NF);
        const float4* m = (const float4*)(mask_in + bb * NF);
        float na = 0.f, nm = 0.f, d = 0.f;
        for (int k = 0; k < NF / 4; k++) {
            float4 x = a[k], y = m[k];
            na += x.x * x.x + x.y * x.y + x.z * x.z + x.w * x.w;
            nm += y.x * y.x + y.y * y.y + y.z * y.z + y.w * y.w;
            d  += x.x * y.x + x.y * y.y + x.z * y.z + x.w * y.w;
        }
        float cv = d / (sqrtf(na) * sqrtf(nm));
        __shared__ float sf[256], sc2[256];
        sf[bb] = fb; sc2[bb] = cv;
        __syncthreads();
        for (int o = 128; o > 0; o >>= 1) {
            if (bb < o) { sf[bb] += sf[bb + o]; sc2[bb] += sc2[bb + o]; }
            __syncthreads();
        }
        // reset counters for next replay (all other blocks finished their reads)
        for (int i = bb; i < NCP; i += 256) { g_cnt1[i] = 0; g_cnt2[i] = 0; }
        if (bb == 0) {
            float focal   = sf[0] / (float)NB;
            float contras = -sc2[0] / (float)NB;
            float insv    = g_ins / (float)NB;
            int epoch = epoch_p[0];
            int back  = back_p[0];
            float loss;
            if (back == 1) {
                loss = focal + 0.25f * contras;
                if (epoch >= 30) loss += 0.2f * insv;
            } else if (back == 2) {
                loss = focal + 0.25f * contras;
            } else {
                loss = focal;
            }
            out[0] = loss;
            g_ins  = 0.f;                          // reset remaining state
            g_done = 0;
        }
    }
}

extern "C" void kernel_launch(void* const* d_in, const int* in_sizes, int n_in,
                              void* d_out, int out_size) {
    const float* inputs   = (const float*)d_in[0];
    const float* mask_in  = (const float*)d_in[1];
    const float* features = (const float*)d_in[2];
    const int*   labels   = (const int*)d_in[3];
    const int*   labels2  = (const int*)d_in[4];
    const int*   indexes  = (const int*)d_in[5];
    const int*   epoch_p  = (const int*)d_in[6];
    const int*   back_p   = (const int*)d_in[7];
    float*       out      = (float*)d_out;

    k_scatter<<<NS / 256, 256>>>(labels, labels2, inputs, indexes);
    k_centroid<<<NC, 512>>>(features);
    k_simfocal<<<2 * NGRP, 512>>>();
    k_insfinal<<<NB, 256>>>(inputs, features, labels, labels2, mask_in, epoch_p, back_p, out);
}

// round 6
// speedup vs baseline: 1.0502x; 1.0179x over previous
#include <cuda_runtime.h>
#include <math.h>

#define NF 256
#define NS 65536
#define NC 2000
#define NCP 2048
#define NB 256
#define CAP 128
#define TEMPv 0.05f
#define INS_TEMPv 0.09f
#define GC 16
#define NGRP (NC / GC)        // 125 class groups
#define INS_SLICES 4
#define INS_BLOCKS (NB * INS_SLICES)

// ---- scratch (device globals; all zero-init, self-resetting each run) ----
__device__ int   g_cnt1[NCP];
__device__ int   g_cnt2[NCP];
__device__ int2  g_list1[NC * CAP];        // (index, labels2[index])
__device__ int2  g_list2[NC * CAP];        // (index, labels[index])
__device__ int   g_targ[NB];
__device__ int   g_targ2[NB];
__device__ float g_centT[NGRP * NF * GC];  // [grp][k][g]: scaled centroids, transposed
__device__ float g_in4[NF * NB];           // packed: float4 (k/4)*NB + b holds k..k+3 of b
__device__ float g_fsum[NB];               // focal softmax denominator partials
__device__ float g_ftgt[NB];               // focal target-class exp
__device__ float g_pos[NB];                // ins pos exp-sum partials
__device__ float g_neg[NB];                // ins neg exp-sum partials
__device__ int   g_np[NB];                 // ins pos counts
__device__ int   g_nn[NB];                 // ins neg counts
__device__ int   g_done;                   // last-block ticket

// ---- K1: scatter into fixed-capacity buckets + pack inputs + targets ----
__global__ void k_scatter(const int* __restrict__ labels, const int* __restrict__ labels2,
                          const float* __restrict__ inputs, const int* __restrict__ indexes) {
    int i = blockIdx.x * blockDim.x + threadIdx.x;
    int c1 = labels[i];
    int c2 = labels2[i];
    int p1 = atomicAdd(&g_cnt1[c1], 1);
    if (p1 < CAP) g_list1[c1 * CAP + p1] = make_int2(i, c2);
    int p2 = atomicAdd(&g_cnt2[c2], 1);
    if (p2 < CAP) g_list2[c2 * CAP + p2] = make_int2(i, c1);
    // pack inputs: sample b, feature k  ->  float slot ((k>>2)*NB + b)*4 + (k&3)
    int b = i >> 8, k = i & 255;
    g_in4[(((k >> 2) * NB) + b) * 4 + (k & 3)] = inputs[i];
    if (i < NB) {
        int idx = indexes[i];
        g_targ[i]  = labels[idx];
        g_targ2[i] = labels2[idx];
    }
}

// ---- K2: scaled class centroids (HBM pass: 64 MB) -> transposed layout ----
__global__ void k_centroid(const float* __restrict__ features) {
    int c   = blockIdx.x;
    int tid = threadIdx.x;
    int r   = tid >> 6;        // 0..7 row slot
    int f4  = tid & 63;        // float4 column
    int cnt = min(g_cnt1[c], CAP);
    __shared__ int js[CAP];
    if (tid < cnt) js[tid] = g_list1[c * CAP + tid].x;
    __syncthreads();
    float4 acc = make_float4(0.f, 0.f, 0.f, 0.f);
    int k = r;
    if (k < cnt) {
        float4 v0 = ((const float4*)(features + (size_t)js[k] * NF))[f4];
        for (k += 8; k < cnt; k += 8) {
            float4 v1 = ((const float4*)(features + (size_t)js[k] * NF))[f4];
            acc.x += v0.x; acc.y += v0.y; acc.z += v0.z; acc.w += v0.w;
            v0 = v1;
        }
        acc.x += v0.x; acc.y += v0.y; acc.z += v0.z; acc.w += v0.w;
    }
    __shared__ float4 sred[8][64];
    sred[r][f4] = acc;
    __syncthreads();
    if (r == 0) {
        float4 s = acc;
#pragma unroll
        for (int w = 1; w < 8; w++) {
            float4 a = sred[w][f4];
            s.x += a.x; s.y += a.y; s.z += a.z; s.w += a.w;
        }
        float sc = (cnt > 0) ? (1.f / (TEMPv * (float)cnt)) : 0.f;
        float* dst = g_centT + (size_t)(c >> 4) * (NF * GC) + (c & 15);
        dst[(4 * f4 + 0) * GC] = s.x * sc;
        dst[(4 * f4 + 1) * GC] = s.y * sc;
        dst[(4 * f4 + 2) * GC] = s.z * sc;
        dst[(4 * f4 + 3) * GC] = s.w * sc;
    }
}

// ---- K3: fused sim GEMM + masked-softmax partials ----
// grid 250 = 125 class-groups x 2 b-halves. Block 512 thr = 128 b x 4 k-quarters.
__global__ void __launch_bounds__(512) k_simfocal() {
    int cg = blockIdx.x >> 1;
    int bh = blockIdx.x & 1;
    int tid = threadIdx.x;
    int bl = tid & 127;
    int kq = tid >> 7;                 // 0..3
    int b  = bh * 128 + bl;

    __shared__ float4 cent4[NF * GC / 4];          // 16 KB, [k][g] transposed
    __shared__ float  sredk[3 * 128 * 17];         // 25.5 KB split-k staging
    float* cent = (float*)cent4;
    const float4* src = (const float4*)(g_centT + (size_t)cg * (NF * GC));
    for (int t = tid; t < NF * GC / 4; t += 512) cent4[t] = src[t];
    __syncthreads();

    unsigned long long acc2[8];
#pragma unroll
    for (int q = 0; q < 8; q++) acc2[q] = 0ULL;

    const float4* xp = (const float4*)g_in4;
    int k4beg = kq * 16;
#pragma unroll 4
    for (int k4 = k4beg; k4 < k4beg + 16; k4++) {
        float4 x = xp[k4 * NB + b];                // coalesced LDG.128
        float xs[4] = {x.x, x.y, x.z, x.w};
#pragma unroll
        for (int j = 0; j < 4; j++) {
            int k = 4 * k4 + j;
            unsigned int xu = __float_as_uint(xs[j]);
            unsigned long long xx;
            asm("mov.b64 %0, {%1, %1};" : "=l"(xx) : "r"(xu));
            const ulonglong2* cp = (const ulonglong2*)(cent + k * GC);
#pragma unroll
            for (int q = 0; q < 4; q++) {
                ulonglong2 cv = cp[q];             // LDS.128 broadcast
                asm("fma.rn.f32x2 %0, %1, %2, %0;" : "+l"(acc2[2*q])   : "l"(cv.x), "l"(xx));
                asm("fma.rn.f32x2 %0, %1, %2, %0;" : "+l"(acc2[2*q+1]) : "l"(cv.y), "l"(xx));
            }
        }
    }

    // ordered split-k combine (stride-17 => bank-conflict-free)
    if (kq) {
        float* dst = sredk + ((kq - 1) * 128 + bl) * 17;
#pragma unroll
        for (int q = 0; q < 8; q++) {
            union { unsigned long long u; float2 f; } a; a.u = acc2[q];
            dst[2 * q]     = a.f.x;
            dst[2 * q + 1] = a.f.y;
        }
    }
    __syncthreads();
    if (kq == 0) {
        float s[16];
#pragma unroll
        for (int q = 0; q < 8; q++) {
            union { unsigned long long u; float2 f; } a; a.u = acc2[q];
            s[2 * q] = a.f.x; s[2 * q + 1] = a.f.y;
        }
#pragma unroll
        for (int r = 0; r < 3; r++) {
            const float* sp2 = sredk + (r * 128 + bl) * 17;
#pragma unroll
            for (int g = 0; g < 16; g++) s[g] += sp2[g];
        }
        int tb = g_targ[b];
        float local = 0.f;
#pragma unroll
        for (int g = 0; g < GC; g++) {
            int c = cg * GC + g;
            if (g_cnt1[c] > 0) {
                float e = expf(s[g]);              // centroid pre-scaled by 1/(TEMP*nums)
                local += e;
                if (c == tb) g_ftgt[b] = e;        // unique writer per b
            }
        }
        atomicAdd(&g_fsum[b], local);
    }
}

// ---- K4: instance loss, 4 slices/sample for MLP + last-block combine/reset ----
__global__ void k_insfinal(const float* __restrict__ inputs, const float* __restrict__ features,
                           const float* __restrict__ mask_in,
                           const int* __restrict__ epoch_p, const int* __restrict__ back_p,
                           float* __restrict__ out) {
    int b  = blockIdx.x >> 2;                      // sample
    int sl = blockIdx.x & 3;                       // slice
    int t  = g_targ[b];
    int t2 = g_targ2[b];
    __shared__ float4 inp[NF / 4];
    if (threadIdx.x < NF / 4)
        inp[threadIdx.x] = ((const float4*)(inputs + b * NF))[threadIdx.x];
    __syncthreads();
    int wid = threadIdx.x >> 5, lane = threadIdx.x & 31;
    int gw = sl * 8 + wid;                         // 0..31: global warp slot, stride 32
    float pos = 0.f, neg = 0.f;
    int np = 0, nn = 0;
    {
        int cnt = min(g_cnt1[t], CAP);
        for (int k = gw; k < cnt; k += 32) {
            int2 e = g_list1[t * CAP + k];         // (j, labels2[j]) — no dependent lookup
            if (e.y != t2) {                       // in_a & ~in_b
                const float4* fr = (const float4*)(features + (size_t)e.x * NF);
                float4 f0 = fr[lane], f1 = fr[lane + 32];
                float4 u0 = inp[lane], u1 = inp[lane + 32];
                float d = f0.x * u0.x + f0.y * u0.y + f0.z * u0.z + f0.w * u0.w
                        + f1.x * u1.x + f1.y * u1.y + f1.z * u1.z + f1.w * u1.w;
                for (int o = 16; o; o >>= 1) d += __shfl_xor_sync(0xFFFFFFFFu, d, o);
                if (lane == 0) { pos += expf(d / INS_TEMPv); np++; }
            }
        }
    }
    {
        int cnt = min(g_cnt2[t2], CAP);
        for (int k = gw; k < cnt; k += 32) {
            int2 e = g_list2[t2 * CAP + k];        // (j, labels[j])
            if (e.y != t) {                        // in_b & ~in_a
                const float4* fr = (const float4*)(features + (size_t)e.x * NF);
                float4 f0 = fr[lane], f1 = fr[lane + 32];
                float4 u0 = inp[lane], u1 = inp[lane + 32];
                float d = f0.x * u0.x + f0.y * u0.y + f0.z * u0.z + f0.w * u0.w
                        + f1.x * u1.x + f1.y * u1.y + f1.z * u1.z + f1.w * u1.w;
                for (int o = 16; o; o >>= 1) d += __shfl_xor_sync(0xFFFFFFFFu, d, o);
                if (lane == 0) { neg += expf(d / INS_TEMPv); nn++; }
            }
        }
    }
    __shared__ float rp[8], rn[8];
    __shared__ int rnp[8], rnn[8];
    if (lane == 0) { rp[wid] = pos; rn[wid] = neg; rnp[wid] = np; rnn[wid] = nn; }
    __syncthreads();
    if (threadIdx.x == 0) {
        float P = 0.f, Ng = 0.f; int NP = 0, NN = 0;
        for (int w = 0; w < 8; w++) { P += rp[w]; Ng += rn[w]; NP += rnp[w]; NN += rnn[w]; }
        if (P  != 0.f) atomicAdd(&g_pos[b], P);
        if (Ng != 0.f) atomicAdd(&g_neg[b], Ng);
        if (NP) atomicAdd(&g_np[b], NP);
        if (NN) atomicAdd(&g_nn[b], NN);
    }

    // ---- last-block final combine + full scratch reset for next replay ----
    __threadfence();
    __shared__ int isLast;
    if (threadIdx.x == 0) {
        int ticket = atomicAdd(&g_done, 1);
        isLast = (ticket == INS_BLOCKS - 1);
    }
    __syncthreads();
    if (isLast) {
        __threadfence();
        int bb = threadIdx.x;
        // ins per sample
        float P = g_pos[bb], Ng = g_neg[bb];
        int NP = g_np[bb], NN = g_nn[bb];
        g_pos[bb] = 0.f; g_neg[bb] = 0.f; g_np[bb] = 0; g_nn[bb] = 0;
        float per = 0.f;
        if (NP > 0 && NN > 0) {
            float insv = P / (P + Ng + 1e-6f);
            per = -logf(insv + 1e-6f) / (float)NP;
        }
        // focal per sample
        float p  = g_ftgt[bb] / (g_fsum[bb] + 1e-6f);
        g_ftgt[bb] = 0.f; g_fsum[bb] = 0.f;
        float om = 1.f - p;
        float fb = -om * om * logf(p + 1e-6f);
        // contras per sample
        const float4* a = (const float4*)(inputs  + bb * NF);
        const float4* m = (const float4*)(mask_in + bb * NF);
        float na = 0.f, nm = 0.f, d = 0.f;
        for (int k = 0; k < NF / 4; k++) {
            float4 x = a[k], y = m[k];
            na += x.x * x.x + x.y * x.y + x.z * x.z + x.w * x.w;
            nm += y.x * y.x + y.y * y.y + y.z * y.z + y.w * y.w;
            d  += x.x * y.x + x.y * y.y + x.z * y.z + x.w * y.w;
        }
        float cv = d / (sqrtf(na) * sqrtf(nm));
        __shared__ float sf[256], sc2[256], si[256];
        sf[bb] = fb; sc2[bb] = cv; si[bb] = per;
        __syncthreads();
        for (int o = 128; o > 0; o >>= 1) {
            if (bb < o) { sf[bb] += sf[bb + o]; sc2[bb] += sc2[bb + o]; si[bb] += si[bb + o]; }
            __syncthreads();
        }
        // reset class counters for next replay
        for (int i = bb; i < NCP; i += 256) { g_cnt1[i] = 0; g_cnt2[i] = 0; }
        if (bb == 0) {
            float focal   = sf[0] / (float)NB;
            float contras = -sc2[0] / (float)NB;
            float insv    = si[0] / (float)NB;
            int epoch = epoch_p[0];
            int back  = back_p[0];
            float loss;
            if (back == 1) {
                loss = focal + 0.25f * contras;
                if (epoch >= 30) loss += 0.2f * insv;
            } else if (back == 2) {
                loss = focal + 0.25f * contras;
            } else {
                loss = focal;
            }
            out[0] = loss;
            g_done = 0;
        }
    }
}

extern "C" void kernel_launch(void* const* d_in, const int* in_sizes, int n_in,
                              void* d_out, int out_size) {
    const float* inputs   = (const float*)d_in[0];
    const float* mask_in  = (const float*)d_in[1];
    const float* features = (const float*)d_in[2];
    const int*   labels   = (const int*)d_in[3];
    const int*   labels2  = (const int*)d_in[4];
    const int*   indexes  = (const int*)d_in[5];
    const int*   epoch_p  = (const int*)d_in[6];
    const int*   back_p   = (const int*)d_in[7];
    float*       out      = (float*)d_out;

    k_scatter<<<NS / 256, 256>>>(labels, labels2, inputs, indexes);
    k_centroid<<<NC, 512>>>(features);
    k_simfocal<<<2 * NGRP, 512>>>();
    k_insfinal<<<INS_BLOCKS, 256>>>(inputs, features, mask_in, epoch_p, back_p, out);
}

// round 7
// speedup vs baseline: 1.1004x; 1.0478x over previous
#include <cuda_runtime.h>
#include <math.h>

#define NF 256
#define NS 65536
#define NC 2000
#define NCP 2048
#define NB 256
#define CAP 128
#define TEMPv 0.05f
#define INS_TEMPv 0.09f
#define GC 16
#define NGRP (NC / GC)        // 125 class groups

// ---- scratch (device globals; all zero-init, self-resetting each run) ----
__device__ int   g_cnt1[NCP];
__device__ int   g_cnt2[NCP];
__device__ int2  g_list1[NC * CAP];        // (index, labels2[index])
__device__ int2  g_list2[NC * CAP];        // (index, labels[index])
__device__ int   g_targ[NB];
__device__ int   g_targ2[NB];
__device__ float g_centT[NGRP * NF * GC];  // [grp][k][g]: scaled centroids, transposed
__device__ float g_in4[NF * NB];           // packed: float4 (k/4)*NB + b holds k..k+3 of b
__device__ float g_fsum[NB];               // focal softmax denominator partials
__device__ float g_ftgt[NB];               // focal target-class exp
__device__ float g_ins;                    // ins_sum
__device__ int   g_done;                   // last-block ticket

// ---- K1: scatter into fixed-capacity buckets + pack inputs + targets ----
__global__ void k_scatter(const int* __restrict__ labels, const int* __restrict__ labels2,
                          const float* __restrict__ inputs, const int* __restrict__ indexes) {
    int i = blockIdx.x * blockDim.x + threadIdx.x;
    int c1 = labels[i];
    int c2 = labels2[i];
    int p1 = atomicAdd(&g_cnt1[c1], 1);
    if (p1 < CAP) g_list1[c1 * CAP + p1] = make_int2(i, c2);
    int p2 = atomicAdd(&g_cnt2[c2], 1);
    if (p2 < CAP) g_list2[c2 * CAP + p2] = make_int2(i, c1);
    int b = i >> 8, k = i & 255;
    g_in4[(((k >> 2) * NB) + b) * 4 + (k & 3)] = inputs[i];
    if (i < NB) {
        int idx = indexes[i];
        g_targ[i]  = labels[idx];
        g_targ2[i] = labels2[idx];
    }
}

// ---- K2: scaled class centroids (HBM pass: 64 MB) -> transposed layout ----
__global__ void k_centroid(const float* __restrict__ features) {
    int c   = blockIdx.x;
    int tid = threadIdx.x;
    int r   = tid >> 6;        // 0..7 row slot
    int f4  = tid & 63;        // float4 column
    int cnt = min(g_cnt1[c], CAP);
    __shared__ int js[CAP];
    if (tid < cnt) js[tid] = g_list1[c * CAP + tid].x;
    __syncthreads();
    float4 acc = make_float4(0.f, 0.f, 0.f, 0.f);
    int k = r;
    if (k < cnt) {
        float4 v0 = ((const float4*)(features + (size_t)js[k] * NF))[f4];
        for (k += 8; k < cnt; k += 8) {
            float4 v1 = ((const float4*)(features + (size_t)js[k] * NF))[f4];
            acc.x += v0.x; acc.y += v0.y; acc.z += v0.z; acc.w += v0.w;
            v0 = v1;
        }
        acc.x += v0.x; acc.y += v0.y; acc.z += v0.z; acc.w += v0.w;
    }
    __shared__ float4 sred[8][64];
    sred[r][f4] = acc;
    __syncthreads();
    if (r == 0) {
        float4 s = acc;
#pragma unroll
        for (int w = 1; w < 8; w++) {
            float4 a = sred[w][f4];
            s.x += a.x; s.y += a.y; s.z += a.z; s.w += a.w;
        }
        float sc = (cnt > 0) ? (1.f / (TEMPv * (float)cnt)) : 0.f;
        float* dst = g_centT + (size_t)(c >> 4) * (NF * GC) + (c & 15);
        dst[(4 * f4 + 0) * GC] = s.x * sc;
        dst[(4 * f4 + 1) * GC] = s.y * sc;
        dst[(4 * f4 + 2) * GC] = s.z * sc;
        dst[(4 * f4 + 3) * GC] = s.w * sc;
    }
}

// ---- K3: fused sim GEMM + masked-softmax partials ----
__global__ void __launch_bounds__(512) k_simfocal() {
    int cg = blockIdx.x >> 1;
    int bh = blockIdx.x & 1;
    int tid = threadIdx.x;
    int bl = tid & 127;
    int kq = tid >> 7;                 // 0..3
    int b  = bh * 128 + bl;

    __shared__ float4 cent4[NF * GC / 4];          // 16 KB, [k][g] transposed
    __shared__ float  sredk[3 * 128 * 17];         // 25.5 KB split-k staging
    float* cent = (float*)cent4;
    const float4* src = (const float4*)(g_centT + (size_t)cg * (NF * GC));
    for (int t = tid; t < NF * GC / 4; t += 512) cent4[t] = src[t];
    __syncthreads();

    unsigned long long acc2[8];
#pragma unroll
    for (int q = 0; q < 8; q++) acc2[q] = 0ULL;

    const float4* xp = (const float4*)g_in4;
    int k4beg = kq * 16;
#pragma unroll 4
    for (int k4 = k4beg; k4 < k4beg + 16; k4++) {
        float4 x = xp[k4 * NB + b];
        float xs[4] = {x.x, x.y, x.z, x.w};
#pragma unroll
        for (int j = 0; j < 4; j++) {
            int k = 4 * k4 + j;
            unsigned int xu = __float_as_uint(xs[j]);
            unsigned long long xx;
            asm("mov.b64 %0, {%1, %1};" : "=l"(xx) : "r"(xu));
            const ulonglong2* cp = (const ulonglong2*)(cent + k * GC);
#pragma unroll
            for (int q = 0; q < 4; q++) {
                ulonglong2 cv = cp[q];
                asm("fma.rn.f32x2 %0, %1, %2, %0;" : "+l"(acc2[2*q])   : "l"(cv.x), "l"(xx));
                asm("fma.rn.f32x2 %0, %1, %2, %0;" : "+l"(acc2[2*q+1]) : "l"(cv.y), "l"(xx));
            }
        }
    }

    if (kq) {
        float* dst = sredk + ((kq - 1) * 128 + bl) * 17;
#pragma unroll
        for (int q = 0; q < 8; q++) {
            union { unsigned long long u; float2 f; } a; a.u = acc2[q];
            dst[2 * q]     = a.f.x;
            dst[2 * q + 1] = a.f.y;
        }
    }
    __syncthreads();
    if (kq == 0) {
        float s[16];
#pragma unroll
        for (int q = 0; q < 8; q++) {
            union { unsigned long long u; float2 f; } a; a.u = acc2[q];
            s[2 * q] = a.f.x; s[2 * q + 1] = a.f.y;
        }
#pragma unroll
        for (int r = 0; r < 3; r++) {
            const float* sp2 = sredk + (r * 128 + bl) * 17;
#pragma unroll
            for (int g = 0; g < 16; g++) s[g] += sp2[g];
        }
        int tb = g_targ[b];
        float local = 0.f;
#pragma unroll
        for (int g = 0; g < GC; g++) {
            int c = cg * GC + g;
            if (g_cnt1[c] > 0) {
                float e = expf(s[g]);
                local += e;
                if (c == tb) g_ftgt[b] = e;
            }
        }
        atomicAdd(&g_fsum[b], local);
    }
}

// ---- K4: ins loss: compact worklists in smem, pipelined gather; + final ----
__global__ void __launch_bounds__(512) k_insfinal(
        const float* __restrict__ inputs, const float* __restrict__ features,
        const float* __restrict__ mask_in,
        const int* __restrict__ epoch_p, const int* __restrict__ back_p,
        float* __restrict__ out) {
    int b   = blockIdx.x;
    int tid = threadIdx.x;
    int t   = g_targ[b];
    int t2  = g_targ2[b];
    __shared__ float4 inp[NF / 4];
    __shared__ int s_listA[CAP], s_listB[CAP];
    __shared__ int s_nA, s_nB;
    if (tid < NF / 4) inp[tid] = ((const float4*)(inputs + b * NF))[tid];
    if (tid == 0) { s_nA = 0; s_nB = 0; }
    __syncthreads();

    // compact filtered worklists (order irrelevant: we only sum exps)
    int cnt1 = min(g_cnt1[t], CAP);
    int cnt2 = min(g_cnt2[t2], CAP);
    if (tid < cnt1) {
        int2 e = g_list1[t * CAP + tid];
        if (e.y != t2) { int p = atomicAdd(&s_nA, 1); s_listA[p] = e.x; }
    }
    if (tid < cnt2) {
        int2 e = g_list2[t2 * CAP + tid];
        if (e.y != t) { int p = atomicAdd(&s_nB, 1); s_listB[p] = e.x; }
    }
    __syncthreads();
    int nA = s_nA, nB = s_nB;

    int lane = tid & 31, wid = tid >> 5;            // 16 warps
    float4 u0 = inp[lane], u1 = inp[lane + 32];
    float pos = 0.f, neg = 0.f;

    // side A: double-buffered gather over compacted list
    {
        int i = wid;
        if (i < nA) {
            const float4* fr = (const float4*)(features + (size_t)s_listA[i] * NF);
            float4 f0 = fr[lane], f1 = fr[lane + 32];
            while (true) {
                int in2 = i + 16;
                bool more = (in2 < nA);
                float4 h0, h1;
                if (more) {
                    const float4* fn = (const float4*)(features + (size_t)s_listA[in2] * NF);
                    h0 = fn[lane]; h1 = fn[lane + 32];
                }
                float d = f0.x * u0.x + f0.y * u0.y + f0.z * u0.z + f0.w * u0.w
                        + f1.x * u1.x + f1.y * u1.y + f1.z * u1.z + f1.w * u1.w;
#pragma unroll
                for (int o = 16; o; o >>= 1) d += __shfl_xor_sync(0xFFFFFFFFu, d, o);
                pos += expf(d / INS_TEMPv);         // uniform across lanes
                if (!more) break;
                i = in2; f0 = h0; f1 = h1;
            }
        }
    }
    // side B
    {
        int i = wid;
        if (i < nB) {
            const float4* fr = (const float4*)(features + (size_t)s_listB[i] * NF);
            float4 f0 = fr[lane], f1 = fr[lane + 32];
            while (true) {
                int in2 = i + 16;
                bool more = (in2 < nB);
                float4 h0, h1;
                if (more) {
                    const float4* fn = (const float4*)(features + (size_t)s_listB[in2] * NF);
                    h0 = fn[lane]; h1 = fn[lane + 32];
                }
                float d = f0.x * u0.x + f0.y * u0.y + f0.z * u0.z + f0.w * u0.w
                        + f1.x * u1.x + f1.y * u1.y + f1.z * u1.z + f1.w * u1.w;
#pragma unroll
                for (int o = 16; o; o >>= 1) d += __shfl_xor_sync(0xFFFFFFFFu, d, o);
                neg += expf(d / INS_TEMPv);
                if (!more) break;
                i = in2; f0 = h0; f1 = h1;
            }
        }
    }

    __shared__ float rp[16], rn[16];
    if (lane == 0) { rp[wid] = pos; rn[wid] = neg; }
    __syncthreads();
    if (tid == 0) {
        float P = 0.f, Ng = 0.f;
#pragma unroll
        for (int w = 0; w < 16; w++) { P += rp[w]; Ng += rn[w]; }
        float per = 0.f;
        if (nA > 0 && nB > 0) {
            float insv = P / (P + Ng + 1e-6f);
            per = -logf(insv + 1e-6f) / (float)nA;
        }
        if (per != 0.f) atomicAdd(&g_ins, per);
    }

    // ---- last-block final combine + full scratch reset for next replay ----
    __threadfence();
    __shared__ int isLast;
    if (tid == 0) {
        int ticket = atomicAdd(&g_done, 1);
        isLast = (ticket == NB - 1);
    }
    __syncthreads();
    if (isLast) {
        __threadfence();
        int bb = tid;
        float fb = 0.f, cv = 0.f;
        if (bb < NB) {
            float p  = g_ftgt[bb] / (g_fsum[bb] + 1e-6f);
            g_ftgt[bb] = 0.f; g_fsum[bb] = 0.f;
            float om = 1.f - p;
            fb = -om * om * logf(p + 1e-6f);
            const float4* a = (const float4*)(inputs  + bb * NF);
            const float4* m = (const float4*)(mask_in + bb * NF);
            float na = 0.f, nm = 0.f, d = 0.f;
            for (int k = 0; k < NF / 4; k++) {
                float4 x = a[k], y = m[k];
                na += x.x * x.x + x.y * x.y + x.z * x.z + x.w * x.w;
                nm += y.x * y.x + y.y * y.y + y.z * y.z + y.w * y.w;
                d  += x.x * y.x + x.y * y.y + x.z * y.z + x.w * y.w;
            }
            cv = d / (sqrtf(na) * sqrtf(nm));
        }
        __shared__ float sf[NB], sc2[NB];
        if (bb < NB) { sf[bb] = fb; sc2[bb] = cv; }
        __syncthreads();
        for (int o = 128; o > 0; o >>= 1) {
            if (bb < o) { sf[bb] += sf[bb + o]; sc2[bb] += sc2[bb + o]; }
            __syncthreads();
        }
        for (int i = bb; i < NCP; i += 512) { g_cnt1[i] = 0; g_cnt2[i] = 0; }
        if (bb == 0) {
            float focal   = sf[0] / (float)NB;
            float contras = -sc2[0] / (float)NB;
            float insv    = g_ins / (float)NB;
            int epoch = epoch_p[0];
            int back  = back_p[0];
            float loss;
            if (back == 1) {
                loss = focal + 0.25f * contras;
                if (epoch >= 30) loss += 0.2f * insv;
            } else if (back == 2) {
                loss = focal + 0.25f * contras;
            } else {
                loss = focal;
            }
            out[0] = loss;
            g_ins  = 0.f;
            g_done = 0;
        }
    }
}

extern "C" void kernel_launch(void* const* d_in, const int* in_sizes, int n_in,
                              void* d_out, int out_size) {
    const float* inputs   = (const float*)d_in[0];
    const float* mask_in  = (const float*)d_in[1];
    const float* features = (const float*)d_in[2];
    const int*   labels   = (const int*)d_in[3];
    const int*   labels2  = (const int*)d_in[4];
    const int*   indexes  = (const int*)d_in[5];
    const int*   epoch_p  = (const int*)d_in[6];
    const int*   back_p   = (const int*)d_in[7];
    float*       out      = (float*)d_out;

    k_scatter<<<NS / 256, 256>>>(labels, labels2, inputs, indexes);
    k_centroid<<<NC, 512>>>(features);
    k_simfocal<<<2 * NGRP, 512>>>();
    k_insfinal<<<NB, 512>>>(inputs, features, mask_in, epoch_p, back_p, out);
}

// round 8
// speedup vs baseline: 1.1295x; 1.0265x over previous
#include <cuda_runtime.h>
#include <math.h>

#define NF 256
#define NS 65536
#define NC 2000
#define NCP 2048
#define NB 256
#define CAP 128
#define TEMPv 0.05f
#define INS_TEMPv 0.09f
#define GC 16
#define NGRP (NC / GC)        // 125 class groups

// ---- scratch (device globals; all zero-init; reset by k_final each run) ----
__device__ int   g_cnt1[NCP];
__device__ int   g_cnt2[NCP];
__device__ int2  g_list1[NC * CAP];        // (index, labels2[index])
__device__ int2  g_list2[NC * CAP];        // (index, labels[index])
__device__ int   g_targ[NB];
__device__ int   g_targ2[NB];
__device__ float g_centT[NGRP * NF * GC];  // [grp][k][g]: scaled centroids, transposed
__device__ float g_in4[NF * NB];           // packed: float4 (k/4)*NB + b holds k..k+3 of b
__device__ float g_fsum[NB];               // focal softmax denominator partials
__device__ float g_ftgt[NB];               // focal target-class exp
__device__ float g_ins;                    // ins_sum

// ---- K1: scatter into fixed-capacity buckets + pack inputs + targets ----
__global__ void k_scatter(const int* __restrict__ labels, const int* __restrict__ labels2,
                          const float* __restrict__ inputs, const int* __restrict__ indexes) {
    int i = blockIdx.x * blockDim.x + threadIdx.x;
    int c1 = labels[i];
    int c2 = labels2[i];
    int p1 = atomicAdd(&g_cnt1[c1], 1);
    if (p1 < CAP) g_list1[c1 * CAP + p1] = make_int2(i, c2);
    int p2 = atomicAdd(&g_cnt2[c2], 1);
    if (p2 < CAP) g_list2[c2 * CAP + p2] = make_int2(i, c1);
    int b = i >> 8, k = i & 255;
    g_in4[(((k >> 2) * NB) + b) * 4 + (k & 3)] = inputs[i];
    if (i < NB) {
        int idx = indexes[i];
        g_targ[i]  = labels[idx];
        g_targ2[i] = labels2[idx];
    }
}

// ---- K2: scaled class centroids (HBM pass: 64 MB) -> transposed layout ----
__global__ void k_centroid(const float* __restrict__ features) {
    int c   = blockIdx.x;
    int tid = threadIdx.x;
    int r   = tid >> 6;        // 0..7 row slot
    int f4  = tid & 63;        // float4 column
    int cnt = min(g_cnt1[c], CAP);
    __shared__ int js[CAP];
    if (tid < cnt) js[tid] = g_list1[c * CAP + tid].x;
    __syncthreads();
    float4 acc = make_float4(0.f, 0.f, 0.f, 0.f);
    int k = r;
    if (k < cnt) {
        float4 v0 = ((const float4*)(features + (size_t)js[k] * NF))[f4];
        for (k += 8; k < cnt; k += 8) {
            float4 v1 = ((const float4*)(features + (size_t)js[k] * NF))[f4];
            acc.x += v0.x; acc.y += v0.y; acc.z += v0.z; acc.w += v0.w;
            v0 = v1;
        }
        acc.x += v0.x; acc.y += v0.y; acc.z += v0.z; acc.w += v0.w;
    }
    __shared__ float4 sred[8][64];
    sred[r][f4] = acc;
    __syncthreads();
    if (r == 0) {
        float4 s = acc;
#pragma unroll
        for (int w = 1; w < 8; w++) {
            float4 a = sred[w][f4];
            s.x += a.x; s.y += a.y; s.z += a.z; s.w += a.w;
        }
        float sc = (cnt > 0) ? (1.f / (TEMPv * (float)cnt)) : 0.f;
        float* dst = g_centT + (size_t)(c >> 4) * (NF * GC) + (c & 15);
        dst[(4 * f4 + 0) * GC] = s.x * sc;
        dst[(4 * f4 + 1) * GC] = s.y * sc;
        dst[(4 * f4 + 2) * GC] = s.z * sc;
        dst[(4 * f4 + 3) * GC] = s.w * sc;
    }
}

// ---- K3: fused sim GEMM + masked-softmax partials ----
__global__ void __launch_bounds__(512) k_simfocal() {
    int cg = blockIdx.x >> 1;
    int bh = blockIdx.x & 1;
    int tid = threadIdx.x;
    int bl = tid & 127;
    int kq = tid >> 7;                 // 0..3
    int b  = bh * 128 + bl;

    __shared__ float4 cent4[NF * GC / 4];          // 16 KB, [k][g] transposed
    __shared__ float  sredk[3 * 128 * 17];         // 25.5 KB split-k staging
    float* cent = (float*)cent4;
    const float4* src = (const float4*)(g_centT + (size_t)cg * (NF * GC));
    for (int t = tid; t < NF * GC / 4; t += 512) cent4[t] = src[t];
    __syncthreads();

    unsigned long long acc2[8];
#pragma unroll
    for (int q = 0; q < 8; q++) acc2[q] = 0ULL;

    const float4* xp = (const float4*)g_in4;
    int k4beg = kq * 16;
#pragma unroll 4
    for (int k4 = k4beg; k4 < k4beg + 16; k4++) {
        float4 x = xp[k4 * NB + b];
        float xs[4] = {x.x, x.y, x.z, x.w};
#pragma unroll
        for (int j = 0; j < 4; j++) {
            int k = 4 * k4 + j;
            unsigned int xu = __float_as_uint(xs[j]);
            unsigned long long xx;
            asm("mov.b64 %0, {%1, %1};" : "=l"(xx) : "r"(xu));
            const ulonglong2* cp = (const ulonglong2*)(cent + k * GC);
#pragma unroll
            for (int q = 0; q < 4; q++) {
                ulonglong2 cv = cp[q];
                asm("fma.rn.f32x2 %0, %1, %2, %0;" : "+l"(acc2[2*q])   : "l"(cv.x), "l"(xx));
                asm("fma.rn.f32x2 %0, %1, %2, %0;" : "+l"(acc2[2*q+1]) : "l"(cv.y), "l"(xx));
            }
        }
    }

    if (kq) {
        float* dst = sredk + ((kq - 1) * 128 + bl) * 17;
#pragma unroll
        for (int q = 0; q < 8; q++) {
            union { unsigned long long u; float2 f; } a; a.u = acc2[q];
            dst[2 * q]     = a.f.x;
            dst[2 * q + 1] = a.f.y;
        }
    }
    __syncthreads();
    if (kq == 0) {
        float s[16];
#pragma unroll
        for (int q = 0; q < 8; q++) {
            union { unsigned long long u; float2 f; } a; a.u = acc2[q];
            s[2 * q] = a.f.x; s[2 * q + 1] = a.f.y;
        }
#pragma unroll
        for (int r = 0; r < 3; r++) {
            const float* sp2 = sredk + (r * 128 + bl) * 17;
#pragma unroll
            for (int g = 0; g < 16; g++) s[g] += sp2[g];
        }
        int tb = g_targ[b];
        float local = 0.f;
#pragma unroll
        for (int g = 0; g < GC; g++) {
            int c = cg * GC + g;
            if (g_cnt1[c] > 0) {
                float e = expf(s[g]);
                local += e;
                if (c == tb) g_ftgt[b] = e;
            }
        }
        atomicAdd(&g_fsum[b], local);
    }
}

// ---- K4: ins loss (runs CONCURRENTLY with centroid+simfocal) ----
__global__ void __launch_bounds__(512) k_ins(
        const float* __restrict__ inputs, const float* __restrict__ features) {
    int b   = blockIdx.x;
    int tid = threadIdx.x;
    int t   = g_targ[b];
    int t2  = g_targ2[b];
    __shared__ float4 inp[NF / 4];
    __shared__ int s_listA[CAP], s_listB[CAP];
    __shared__ int s_nA, s_nB;
    if (tid < NF / 4) inp[tid] = ((const float4*)(inputs + b * NF))[tid];
    if (tid == 0) { s_nA = 0; s_nB = 0; }
    __syncthreads();

    // compact filtered worklists (order irrelevant: we only sum exps)
    int cnt1 = min(g_cnt1[t], CAP);
    int cnt2 = min(g_cnt2[t2], CAP);
    if (tid < cnt1) {
        int2 e = g_list1[t * CAP + tid];
        if (e.y != t2) { int p = atomicAdd(&s_nA, 1); s_listA[p] = e.x; }
    }
    if (tid < cnt2) {
        int2 e = g_list2[t2 * CAP + tid];
        if (e.y != t) { int p = atomicAdd(&s_nB, 1); s_listB[p] = e.x; }
    }
    __syncthreads();
    int nA = s_nA, nB = s_nB;

    int lane = tid & 31, wid = tid >> 5;            // 16 warps
    float4 u0 = inp[lane], u1 = inp[lane + 32];
    float pos = 0.f, neg = 0.f;

    {   // side A: double-buffered gather over compacted list
        int i = wid;
        if (i < nA) {
            const float4* fr = (const float4*)(features + (size_t)s_listA[i] * NF);
            float4 f0 = fr[lane], f1 = fr[lane + 32];
            while (true) {
                int in2 = i + 16;
                bool more = (in2 < nA);
                float4 h0, h1;
                if (more) {
                    const float4* fn = (const float4*)(features + (size_t)s_listA[in2] * NF);
                    h0 = fn[lane]; h1 = fn[lane + 32];
                }
                float d = f0.x * u0.x + f0.y * u0.y + f0.z * u0.z + f0.w * u0.w
                        + f1.x * u1.x + f1.y * u1.y + f1.z * u1.z + f1.w * u1.w;
#pragma unroll
                for (int o = 16; o; o >>= 1) d += __shfl_xor_sync(0xFFFFFFFFu, d, o);
                pos += expf(d / INS_TEMPv);
                if (!more) break;
                i = in2; f0 = h0; f1 = h1;
            }
        }
    }
    {   // side B
        int i = wid;
        if (i < nB) {
            const float4* fr = (const float4*)(features + (size_t)s_listB[i] * NF);
            float4 f0 = fr[lane], f1 = fr[lane + 32];
            while (true) {
                int in2 = i + 16;
                bool more = (in2 < nB);
                float4 h0, h1;
                if (more) {
                    const float4* fn = (const float4*)(features + (size_t)s_listB[in2] * NF);
                    h0 = fn[lane]; h1 = fn[lane + 32];
                }
                float d = f0.x * u0.x + f0.y * u0.y + f0.z * u0.z + f0.w * u0.w
                        + f1.x * u1.x + f1.y * u1.y + f1.z * u1.z + f1.w * u1.w;
#pragma unroll
                for (int o = 16; o; o >>= 1) d += __shfl_xor_sync(0xFFFFFFFFu, d, o);
                neg += expf(d / INS_TEMPv);
                if (!more) break;
                i = in2; f0 = h0; f1 = h1;
            }
        }
    }

    __shared__ float rp[16], rn[16];
    if (lane == 0) { rp[wid] = pos; rn[wid] = neg; }
    __syncthreads();
    if (tid == 0) {
        float P = 0.f, Ng = 0.f;
#pragma unroll
        for (int w = 0; w < 16; w++) { P += rp[w]; Ng += rn[w]; }
        float per = 0.f;
        if (nA > 0 && nB > 0) {
            float insv = P / (P + Ng + 1e-6f);
            per = -logf(insv + 1e-6f) / (float)nA;
        }
        if (per != 0.f) atomicAdd(&g_ins, per);
    }
}

// ---- K5: final combine (after join) + full scratch reset for next replay ----
__global__ void k_final(const float* __restrict__ inputs, const float* __restrict__ mask_in,
                        const int* __restrict__ epoch_p, const int* __restrict__ back_p,
                        float* __restrict__ out) {
    int bb = threadIdx.x;
    float p  = g_ftgt[bb] / (g_fsum[bb] + 1e-6f);
    g_ftgt[bb] = 0.f; g_fsum[bb] = 0.f;               // reset
    float om = 1.f - p;
    float fb = -om * om * logf(p + 1e-6f);
    const float4* a = (const float4*)(inputs  + bb * NF);
    const float4* m = (const float4*)(mask_in + bb * NF);
    float na = 0.f, nm = 0.f, d = 0.f;
    for (int k = 0; k < NF / 4; k++) {
        float4 x = a[k], y = m[k];
        na += x.x * x.x + x.y * x.y + x.z * x.z + x.w * x.w;
        nm += y.x * y.x + y.y * y.y + y.z * y.z + y.w * y.w;
        d  += x.x * y.x + x.y * y.y + x.z * y.z + x.w * y.w;
    }
    float cv = d / (sqrtf(na) * sqrtf(nm));
    __shared__ float sf[NB], sc2[NB];
    sf[bb] = fb; sc2[bb] = cv;
    __syncthreads();
    for (int o = 128; o > 0; o >>= 1) {
        if (bb < o) { sf[bb] += sf[bb + o]; sc2[bb] += sc2[bb + o]; }
        __syncthreads();
    }
    for (int i = bb; i < NCP; i += 256) { g_cnt1[i] = 0; g_cnt2[i] = 0; }  // reset
    if (bb == 0) {
        float focal   = sf[0] / (float)NB;
        float contras = -sc2[0] / (float)NB;
        float insv    = g_ins / (float)NB;
        g_ins = 0.f;                                   // reset
        int epoch = epoch_p[0];
        int back  = back_p[0];
        float loss;
        if (back == 1) {
            loss = focal + 0.25f * contras;
            if (epoch >= 30) loss += 0.2f * insv;
        } else if (back == 2) {
            loss = focal + 0.25f * contras;
        } else {
            loss = focal;
        }
        out[0] = loss;
    }
}

extern "C" void kernel_launch(void* const* d_in, const int* in_sizes, int n_in,
                              void* d_out, int out_size) {
    const float* inputs   = (const float*)d_in[0];
    const float* mask_in  = (const float*)d_in[1];
    const float* features = (const float*)d_in[2];
    const int*   labels   = (const int*)d_in[3];
    const int*   labels2  = (const int*)d_in[4];
    const int*   indexes  = (const int*)d_in[5];
    const int*   epoch_p  = (const int*)d_in[6];
    const int*   back_p   = (const int*)d_in[7];
    float*       out      = (float*)d_out;

    // one-time host-side resources (no device memory involved)
    static cudaStream_t s_ins = nullptr;
    static cudaEvent_t  evFork = nullptr, evJoin = nullptr;
    if (s_ins == nullptr) {
        cudaStreamCreateWithFlags(&s_ins, cudaStreamNonBlocking);
        cudaEventCreateWithFlags(&evFork, cudaEventDisableTiming);
        cudaEventCreateWithFlags(&evJoin, cudaEventDisableTiming);
    }

    k_scatter<<<NS / 256, 256>>>(labels, labels2, inputs, indexes);

    // fork: ins branch runs concurrently with centroid+simfocal
    cudaEventRecord(evFork, 0);
    cudaStreamWaitEvent(s_ins, evFork, 0);
    k_ins<<<NB, 512, 0, s_ins>>>(inputs, features);
    cudaEventRecord(evJoin, s_ins);

    k_centroid<<<NC, 512>>>(features);
    k_simfocal<<<2 * NGRP, 512>>>();

    // join + final combine
    cudaStreamWaitEvent(0, evJoin, 0);
    k_final<<<1, 256>>>(inputs, mask_in, epoch_p, back_p, out);
}